// round 3
// baseline (speedup 1.0000x reference)
#include <cuda_runtime.h>
#include <cstddef>

#define B_   16
#define C_   64
#define HW_  96
#define CC   8      // ci chunk per smem stage

typedef unsigned long long ull;

// ---------------- scratch (static device globals: allocation-rule safe) ------
__device__ float g_kf[(size_t)B_ * C_ * HW_ * HW_];
__device__ float g_qf[(size_t)B_ * C_ * HW_ * HW_];
__device__ float g_vf[(size_t)B_ * C_ * HW_ * HW_];
__device__ float g_sc[(size_t)B_ * C_ * 576];
__device__ float g_scp[(size_t)4 * B_ * 9 * 64 * 64];   // scores partials [ch][b][k][c][d]

// ---------------- packed fp32x2 helpers (sm_103a FFMA2) ----------------------
__device__ __forceinline__ ull pack2(float a, float b) {
    ull r; asm("mov.b64 %0, {%1, %2};" : "=l"(r) : "f"(a), "f"(b)); return r;
}
__device__ __forceinline__ void fma2(ull& d, ull a, ull b) {
    asm("fma.rn.f32x2 %0, %1, %2, %3;" : "=l"(d) : "l"(a), "l"(b), "l"(d));
}
__device__ __forceinline__ float2 unpack2(ull v) {
    float2 r; asm("mov.b64 {%0, %1}, %2;" : "=f"(r.x), "=f"(r.y) : "l"(v)); return r;
}

// ---------------- 3x3 same-pad conv, FFMA2 co-pair packed --------------------
// out[b,co,y,x] = sum_{ci,kh,kw} xin[b,ci,y+kh-1,x+kw-1] * w[co, ci*9+kh*3+kw]
// Thread: 4 horizontal pixels x 8 co-pairs (16 co). Block: 16x16 tile, all 64 co.
__global__ __launch_bounds__(256, 2) void conv3x3_k(
    const float* __restrict__ xin, const float* __restrict__ wgt,
    float* __restrict__ out, int wBatchStride)
{
    __shared__ float sin_[CC * 18 * 20];              // rows padded 18->20 (16B align)
    __shared__ __align__(16) ull wsm[CC * 32 * 3 * 4]; // [ci][copair][kh][4 pairs]

    const int b  = blockIdx.z;
    const int bx = blockIdx.x * 16, by = blockIdx.y * 16;
    const int t  = threadIdx.x;
    const int pg   = t >> 6;            // co-pair group (8 pairs each)
    const int slot = t & 63;
    const int lx   = (slot & 3) * 4;    // pixel-x base within tile
    const int py   = slot >> 2;         // pixel-y within tile

    const float* xb = xin + (size_t)b * C_ * HW_ * HW_;
    const float* wb = wgt + (size_t)b * wBatchStride;

    ull acc[8][4];
#pragma unroll
    for (int i = 0; i < 8; i++)
#pragma unroll
        for (int j = 0; j < 4; j++) acc[i][j] = 0ull;

#pragma unroll 1
    for (int c0 = 0; c0 < C_; c0 += CC) {
        __syncthreads();
        // stage input tile (CC x 18 x 18 into pitch-20 rows, zero-padded at border)
        for (int idx = t; idx < CC * 324; idx += 256) {
            int ci = idx / 324, rem = idx % 324;
            int r = rem / 18, cx = rem % 18;
            int gy = by + r - 1, gx = bx + cx - 1;
            float v = 0.f;
            if (gy >= 0 && gy < HW_ && gx >= 0 && gx < HW_)
                v = xb[((size_t)(c0 + ci) * HW_ + gy) * HW_ + gx];
            sin_[ci * 360 + r * 20 + cx] = v;
        }
        // stage weights dup-interleaved: wsm[ci][cp][kh][p] = (w[2cp][kh*3+p], w[2cp+1][kh*3+p])
        for (int idx = t; idx < CC * 32 * 12; idx += 256) {
            int p = idx & 3, q = idx >> 2;
            int kh = q % 3; q /= 3;
            int cp = q & 31; int ci = q >> 5;
            ull v = 0ull;
            if (p < 3) {
                int k = kh * 3 + p, co = cp * 2;
                v = pack2(wb[co * 576 + (c0 + ci) * 9 + k],
                          wb[(co + 1) * 576 + (c0 + ci) * 9 + k]);
            }
            wsm[idx] = v;
        }
        __syncthreads();

#pragma unroll 1
        for (int ci = 0; ci < CC; ci++) {
#pragma unroll
            for (int kh = 0; kh < 3; kh++) {
                const float* rp = sin_ + ci * 360 + (py + kh) * 20 + lx;
                float4 a = *(const float4*)rp;
                float2 bq = *(const float2*)(rp + 4);
                ull vv[6];
                vv[0] = pack2(a.x, a.x);  vv[1] = pack2(a.y, a.y);
                vv[2] = pack2(a.z, a.z);  vv[3] = pack2(a.w, a.w);
                vv[4] = pack2(bq.x, bq.x); vv[5] = pack2(bq.y, bq.y);
                const ull* wbase = wsm + ((ci * 32 + pg * 8) * 3 + kh) * 4;
#pragma unroll
                for (int cpl = 0; cpl < 8; cpl++) {
                    const ulonglong2* wpp = (const ulonglong2*)(wbase + cpl * 12);
                    ulonglong2 wA = wpp[0], wB = wpp[1];
#pragma unroll
                    for (int p = 0; p < 4; p++) {
                        fma2(acc[cpl][p], vv[p],     wA.x);
                        fma2(acc[cpl][p], vv[p + 1], wA.y);
                        fma2(acc[cpl][p], vv[p + 2], wB.x);
                    }
                }
            }
        }
    }

    const int y = by + py;
#pragma unroll
    for (int cpl = 0; cpl < 8; cpl++) {
        int co = (pg * 8 + cpl) * 2;
        float* o0 = out + (((size_t)(b * C_ + co)) * HW_ + y) * HW_ + bx + lx;
        float* o1 = o0 + (size_t)HW_ * HW_;
#pragma unroll
        for (int p = 0; p < 4; p++) {
            float2 v = unpack2(acc[cpl][p]);
            o0[p] = v.x;
            o1[p] = v.y;
        }
    }
}

// ---------------- scores partials: per (b,k,chunk) 64x64 Gram over 8 hp rows -
// scp[ch][b][k][c][d] = sum_{hp in chunk, wp} kf[b,c,hp*3+kh,wp*3+kw]*qf[b,d,...]
__global__ __launch_bounds__(256) void scores_k(
    const float* __restrict__ kf, const float* __restrict__ qf,
    float* __restrict__ scp)
{
    __shared__ float ks[C_][33];
    __shared__ float qs[C_][33];

    const int k  = blockIdx.x;          // 0..8
    const int ch = blockIdx.y;          // 0..3
    const int b  = blockIdx.z;          // 0..15
    const int kh = k / 3, kw = k - kh * 3;
    const int t = threadIdx.x;
    const int tc = t >> 4, td = t & 15;

    const float* kb = kf + (size_t)b * C_ * HW_ * HW_;
    const float* qb = qf + (size_t)b * C_ * HW_ * HW_;

    float acc[4][4] = {};

#pragma unroll 1
    for (int hp = ch * 8; hp < ch * 8 + 8; hp++) {
        __syncthreads();
        const int y = hp * 3 + kh;
        for (int idx = t; idx < C_ * 32; idx += 256) {
            int c = idx >> 5, wp = idx & 31;
            int x = wp * 3 + kw;
            size_t off = ((size_t)c * HW_ + y) * HW_ + x;
            ks[c][wp] = kb[off];
            qs[c][wp] = qb[off];
        }
        __syncthreads();
#pragma unroll 4
        for (int l = 0; l < 32; l++) {
            float kv[4], qv[4];
#pragma unroll
            for (int i = 0; i < 4; i++) { kv[i] = ks[tc * 4 + i][l]; qv[i] = qs[td * 4 + i][l]; }
#pragma unroll
            for (int i = 0; i < 4; i++)
#pragma unroll
                for (int j = 0; j < 4; j++)
                    acc[i][j] += kv[i] * qv[j];
        }
    }

    float* p = scp + ((size_t)((ch * 16 + b) * 9 + k)) * 4096;
#pragma unroll
    for (int i = 0; i < 4; i++)
#pragma unroll
        for (int j = 0; j < 4; j++)
            p[(tc * 4 + i) * 64 + (td * 4 + j)] = acc[i][j];
}

// ---------------- softmax over 576 per (b,d): sum partials, scale, softmax ---
__global__ __launch_bounds__(256) void softmax_k(
    const float* __restrict__ scp, float* __restrict__ s)
{
    __shared__ float red[8];
    const int b = blockIdx.x >> 6, d = blockIdx.x & 63;
    const int t = threadIdx.x;
    const float scale = 1.f / 24.f;     // 1/sqrt(576)

    float v[3];
#pragma unroll
    for (int u = 0; u < 3; u++) {
        int e = t + u * 256;
        if (e < 576) {
            int c = e / 9, k = e - c * 9;
            float sum = 0.f;
#pragma unroll
            for (int chn = 0; chn < 4; chn++)
                sum += scp[((size_t)((chn * 16 + b) * 9 + k)) * 4096 + c * 64 + d];
            v[u] = sum * scale;
        } else v[u] = -3.4e38f;
    }

    float m = fmaxf(fmaxf(v[0], v[1]), v[2]);
#pragma unroll
    for (int o = 16; o; o >>= 1) m = fmaxf(m, __shfl_xor_sync(0xffffffffu, m, o));
    if ((t & 31) == 0) red[t >> 5] = m;
    __syncthreads();
    m = fmaxf(fmaxf(fmaxf(red[0], red[1]), fmaxf(red[2], red[3])),
              fmaxf(fmaxf(red[4], red[5]), fmaxf(red[6], red[7])));
    __syncthreads();

    float e0 = __expf(v[0] - m), e1 = __expf(v[1] - m);
    float e2 = (t + 512) < 576 ? __expf(v[2] - m) : 0.f;
    float sum = e0 + e1 + e2;
#pragma unroll
    for (int o = 16; o; o >>= 1) sum += __shfl_xor_sync(0xffffffffu, sum, o);
    if ((t & 31) == 0) red[t >> 5] = sum;
    __syncthreads();
    sum = red[0] + red[1] + red[2] + red[3] + red[4] + red[5] + red[6] + red[7];

    float inv = 1.f / sum;
    float* p = s + (size_t)(b * C_ + d) * 576;
    p[t] = e0 * inv;
    p[t + 256] = e1 * inv;
    if (t + 512 < 576) p[t + 512] = e2 * inv;
}

// ---------------- launch -----------------------------------------------------
extern "C" void kernel_launch(void* const* d_in, const int* in_sizes, int n_in,
                              void* d_out, int out_size)
{
    const float* x1 = (const float*)d_in[0];
    const float* x2 = (const float*)d_in[1];
    const float* w1 = (const float*)d_in[2];
    const float* w2 = (const float*)d_in[3];
    const float* w3 = (const float*)d_in[4];
    float* out = (float*)d_out;

    float *kf, *qf, *vf, *sc, *scp;
    cudaGetSymbolAddress((void**)&kf, g_kf);
    cudaGetSymbolAddress((void**)&qf, g_qf);
    cudaGetSymbolAddress((void**)&vf, g_vf);
    cudaGetSymbolAddress((void**)&sc, g_sc);
    cudaGetSymbolAddress((void**)&scp, g_scp);

    dim3 g(HW_ / 16, HW_ / 16, B_);
    dim3 blk(256, 1, 1);

    conv3x3_k<<<g, blk>>>(x1, w1, kf, 0);
    conv3x3_k<<<g, blk>>>(x2, w2, qf, 0);
    conv3x3_k<<<g, blk>>>(x1, w3, vf, 0);
    scores_k<<<dim3(9, 4, B_), 256>>>(kf, qf, scp);
    softmax_k<<<B_ * C_, 256>>>(scp, sc);
    conv3x3_k<<<g, blk>>>(vf, sc, out, C_ * 576);
}

// round 8
// speedup vs baseline: 2.2470x; 2.2470x over previous
#include <cuda_runtime.h>
#include <cuda_fp16.h>
#include <cstddef>

typedef unsigned int u32;

#define B_   16
#define C_   64
#define HW_  96

// ---------------- scratch ----------------------------------------------------
__device__ float g_kf[(size_t)B_ * C_ * HW_ * HW_];
__device__ float g_qf[(size_t)B_ * C_ * HW_ * HW_];
__device__ float g_sc[(size_t)B_ * C_ * 576];
__device__ float g_scp[(size_t)4 * B_ * 9 * 64 * 64];
// pixel-major fp16 hi/lo: [img][y][x][ci]; img 0-15:x1, 16-31:x2, 32-47:vf
__device__ __half g_Xh[(size_t)48 * HW_ * HW_ * 64];
__device__ __half g_Xl[(size_t)48 * HW_ * HW_ * 64];
// weight rows [row][ci]: 0-575 w1, 576-1151 w2, 1152-1727 w3, 1728+ dyn (576/b)
__device__ __half g_Bh[(size_t)11008 * 64];
__device__ __half g_Bl[(size_t)11008 * 64];

// ---------------- mma helpers ------------------------------------------------
__device__ __forceinline__ u32 s2u(const void* p) {
    u32 a; asm("{ .reg .u64 t; cvta.to.shared.u64 t, %1; cvt.u32.u64 %0, t; }" : "=r"(a) : "l"(p));
    return a;
}
__device__ __forceinline__ void ldsm4(u32& r0, u32& r1, u32& r2, u32& r3, u32 addr) {
    asm volatile("ldmatrix.sync.aligned.m8n8.x4.shared.b16 {%0,%1,%2,%3}, [%4];"
        : "=r"(r0), "=r"(r1), "=r"(r2), "=r"(r3) : "r"(addr));
}
__device__ __forceinline__ void mma16816(float* d, const u32* a, const u32* b) {
    asm volatile("mma.sync.aligned.m16n8k16.row.col.f32.f16.f16.f32 "
        "{%0,%1,%2,%3}, {%4,%5,%6,%7}, {%8,%9}, {%0,%1,%2,%3};"
        : "+f"(d[0]), "+f"(d[1]), "+f"(d[2]), "+f"(d[3])
        : "r"(a[0]), "r"(a[1]), "r"(a[2]), "r"(a[3]), "r"(b[0]), "r"(b[1]));
}

// smem layout (bytes): halo A hi[180][72h], lo; B hi[64][72h], lo. 144B row pitch.
#define AH_OFF 0
#define AL_OFF 25920
#define BH_OFF 51840
#define BL_OFF 61056
#define SMEMSZ 70272

// ---------------- mma conv: 16x8 px tile x 64 co, 9 taps, hh+hl+lh -----------
__global__ void __launch_bounds__(256, 2) conv_mma_k(
    const __half* __restrict__ Xh, const __half* __restrict__ Xl,
    const __half* __restrict__ Bh, const __half* __restrict__ Bl,
    int aBase, int bRowBase, int bRowStride, int mode,
    float* __restrict__ outF, __half* __restrict__ Vh, __half* __restrict__ Vl)
{
    extern __shared__ __align__(16) char sm[];
    const u32 sb = s2u(sm);
    const int t = threadIdx.x, lane = t & 31, wid = t >> 5;
    const int m0 = (wid & 3) * 32, n0 = (wid >> 2) * 32;
    const int b = blockIdx.z;
    const int x0 = blockIdx.x * 16, y0 = blockIdx.y * 8;
    const int brow = bRowBase + b * bRowStride;

    // ---- stage halo once: 180 rows (10y x 18x), 8 x 16B segs, hi+lo ----
    {
        const __half* XhB = Xh + (size_t)(aBase + b) * 9216 * 64;
        const __half* XlB = Xl + (size_t)(aBase + b) * 9216 * 64;
        for (int i = t; i < 1440; i += 256) {
            int row = i >> 3, seg = i & 7;
            int hy = row / 18, hx = row - hy * 18;
            int gy = y0 + hy - 1, gx = x0 + hx - 1;
            float4 vh = make_float4(0.f, 0.f, 0.f, 0.f), vl = vh;
            if ((unsigned)gy < 96u && (unsigned)gx < 96u) {
                size_t g = ((size_t)gy * 96 + gx) * 64 + seg * 8;
                vh = *(const float4*)(XhB + g);
                vl = *(const float4*)(XlB + g);
            }
            *(float4*)(sm + AH_OFF + row * 144 + seg * 16) = vh;
            *(float4*)(sm + AL_OFF + row * 144 + seg * 16) = vl;
        }
    }

    // lane geometry for ldmatrix.x4
    const int aRowL = (lane & 7) + 8 * ((lane >> 3) & 1); // + f*16 + m0
    const int aKb   = 16 * (lane >> 4);
    const int bCoL  = (lane & 7) + 8 * (lane >> 4);       // + j*16 + n0
    const int bKb   = 16 * ((lane >> 3) & 1);

    float acc[2][4][4];
#pragma unroll
    for (int i = 0; i < 2; i++)
#pragma unroll
        for (int j = 0; j < 4; j++)
#pragma unroll
            for (int k = 0; k < 4; k++) acc[i][j][k] = 0.f;

#pragma unroll 1
    for (int tap = 0; tap < 9; tap++) {
        __syncthreads();   // prior tap's ldmatrix done before B overwrite
        // ---- stage B tap: 64 rows x 8 segs, hi+lo ----
        for (int i = t; i < 512; i += 256) {
            int co = i >> 3, seg = i & 7;
            size_t g = (size_t)(brow + tap * 64 + co) * 64 + seg * 8;
            *(float4*)(sm + BH_OFF + co * 144 + seg * 16) = *(const float4*)(Bh + g);
            *(float4*)(sm + BL_OFF + co * 144 + seg * 16) = *(const float4*)(Bl + g);
        }
        __syncthreads();

        const int kh = tap / 3, kw = tap - kh * 3;
        u32 aAddr[2], bAddr[2];
#pragma unroll
        for (int f = 0; f < 2; f++) {
            int px = m0 + f * 16 + aRowL;
            int r = ((px >> 4) + kh) * 18 + (px & 15) + kw;
            aAddr[f] = sb + AH_OFF + r * 144 + aKb;
        }
#pragma unroll
        for (int j = 0; j < 2; j++)
            bAddr[j] = sb + BH_OFF + (n0 + j * 16 + bCoL) * 144 + bKb;

#pragma unroll
        for (int ks = 0; ks < 4; ks++) {
            u32 Ah[2][4], Al[2][4], Bhf[2][4], Blf[2][4];
#pragma unroll
            for (int f = 0; f < 2; f++) {
                u32 a = aAddr[f] + ks * 32;
                ldsm4(Ah[f][0], Ah[f][1], Ah[f][2], Ah[f][3], a);
                ldsm4(Al[f][0], Al[f][1], Al[f][2], Al[f][3], a + (AL_OFF - AH_OFF));
            }
#pragma unroll
            for (int j = 0; j < 2; j++) {
                u32 a = bAddr[j] + ks * 32;
                ldsm4(Bhf[j][0], Bhf[j][1], Bhf[j][2], Bhf[j][3], a);
                ldsm4(Blf[j][0], Blf[j][1], Blf[j][2], Blf[j][3], a + (BL_OFF - BH_OFF));
            }
#pragma unroll
            for (int mf = 0; mf < 2; mf++)
#pragma unroll
                for (int nf = 0; nf < 4; nf++) {
                    const u32* bh = &Bhf[nf >> 1][(nf & 1) * 2];
                    const u32* bl = &Blf[nf >> 1][(nf & 1) * 2];
                    mma16816(acc[mf][nf], Ah[mf], bh);
                    mma16816(acc[mf][nf], Ah[mf], bl);
                    mma16816(acc[mf][nf], Al[mf], bh);
                }
        }
    }

    // ---- epilogue ----
    const int g = lane >> 2, tt = lane & 3;
    if (mode == 0) {
        float* ob = outF + (size_t)b * C_ * 9216;
#pragma unroll
        for (int mf = 0; mf < 2; mf++)
#pragma unroll
            for (int nf = 0; nf < 4; nf++) {
                int co = n0 + nf * 8 + 2 * tt;
#pragma unroll
                for (int h = 0; h < 2; h++) {
                    int px = m0 + mf * 16 + g + h * 8;
                    int y = y0 + (px >> 4), x = x0 + (px & 15);
                    ob[(size_t)co * 9216 + y * 96 + x]       = acc[mf][nf][2 * h];
                    ob[(size_t)(co + 1) * 9216 + y * 96 + x] = acc[mf][nf][2 * h + 1];
                }
            }
    } else {
#pragma unroll
        for (int mf = 0; mf < 2; mf++)
#pragma unroll
            for (int nf = 0; nf < 4; nf++) {
                int co = n0 + nf * 8 + 2 * tt;
#pragma unroll
                for (int h = 0; h < 2; h++) {
                    int px = m0 + mf * 16 + g + h * 8;
                    int y = y0 + (px >> 4), x = x0 + (px & 15);
                    size_t ad = ((size_t)(32 + b) * 9216 + (size_t)y * 96 + x) * 64 + co;
                    float v0 = acc[mf][nf][2 * h], v1 = acc[mf][nf][2 * h + 1];
                    __half h0 = __float2half(v0), h1 = __float2half(v1);
                    __half l0 = __float2half(v0 - __half2float(h0));
                    __half l1 = __float2half(v1 - __half2float(h1));
                    *(__half2*)(Vh + ad) = __halves2half2(h0, h1);
                    *(__half2*)(Vl + ad) = __halves2half2(l0, l1);
                }
            }
    }
}

// ---------------- input transpose + fp16 hi/lo split -------------------------
__global__ __launch_bounds__(256) void convert_x_k(
    const float* __restrict__ x1, const float* __restrict__ x2,
    __half* __restrict__ Xh, __half* __restrict__ Xl)
{
    __shared__ float smt[96 * 65];
    const int y = blockIdx.x, b = blockIdx.y, src = blockIdx.z;
    const int t = threadIdx.x;
    const float* xp = (src ? x2 : x1) + (size_t)b * C_ * 9216 + (size_t)y * 96;
    for (int idx = t; idx < 64 * 96; idx += 256) {
        int ci = idx / 96, x = idx - ci * 96;
        smt[x * 65 + ci] = xp[(size_t)ci * 9216 + x];
    }
    __syncthreads();
    size_t base = ((size_t)((src * 16 + b) * 96 + y)) * 96 * 64;
    for (int idx = t; idx < 96 * 64; idx += 256) {
        int x = idx >> 6, ci = idx & 63;
        float v = smt[x * 65 + ci];
        __half h = __float2half(v);
        Xh[base + idx] = h;
        Xl[base + idx] = __float2half(v - __half2float(h));
    }
}

// ---------------- weight gather + fp16 hi/lo split ---------------------------
// row = rowBase + b*rowBS + tap*64 + co ; val = w[b*sStride + co*576 + ci*9 + tap]
__global__ __launch_bounds__(64) void convert_w_k(
    const float* __restrict__ w, __half* __restrict__ Bh, __half* __restrict__ Bl,
    int rowBase, int sStride, int rowBS)
{
    const int tap = blockIdx.x >> 6, co = blockIdx.x & 63, b = blockIdx.y, ci = threadIdx.x;
    float v = w[(size_t)b * sStride + co * 576 + ci * 9 + tap];
    size_t row = (size_t)(rowBase + b * rowBS + tap * 64 + co);
    __half h = __float2half(v);
    Bh[row * 64 + ci] = h;
    Bl[row * 64 + ci] = __float2half(v - __half2float(h));
}

// ---------------- scores partials --------------------------------------------
__global__ __launch_bounds__(256) void scores_k(
    const float* __restrict__ kf, const float* __restrict__ qf, float* __restrict__ scp)
{
    __shared__ float ks[C_][33];
    __shared__ float qs[C_][33];
    const int k = blockIdx.x, ch = blockIdx.y, b = blockIdx.z;
    const int kh = k / 3, kw = k - kh * 3;
    const int t = threadIdx.x;
    const int tc = t >> 4, td = t & 15;
    const float* kb = kf + (size_t)b * C_ * 9216;
    const float* qb = qf + (size_t)b * C_ * 9216;
    float acc[4][4] = {};
#pragma unroll 1
    for (int hp = ch * 8; hp < ch * 8 + 8; hp++) {
        __syncthreads();
        const int y = hp * 3 + kh;
        for (int idx = t; idx < C_ * 32; idx += 256) {
            int c = idx >> 5, wp = idx & 31;
            size_t off = ((size_t)c * 96 + y) * 96 + wp * 3 + kw;
            ks[c][wp] = kb[off];
            qs[c][wp] = qb[off];
        }
        __syncthreads();
#pragma unroll 4
        for (int l = 0; l < 32; l++) {
            float kv[4], qv[4];
#pragma unroll
            for (int i = 0; i < 4; i++) { kv[i] = ks[tc * 4 + i][l]; qv[i] = qs[td * 4 + i][l]; }
#pragma unroll
            for (int i = 0; i < 4; i++)
#pragma unroll
                for (int j = 0; j < 4; j++) acc[i][j] += kv[i] * qv[j];
        }
    }
    float* p = scp + ((size_t)((ch * 16 + b) * 9 + k)) * 4096;
#pragma unroll
    for (int i = 0; i < 4; i++)
#pragma unroll
        for (int j = 0; j < 4; j++)
            p[(tc * 4 + i) * 64 + (td * 4 + j)] = acc[i][j];
}

// ---------------- softmax ----------------------------------------------------
__global__ __launch_bounds__(256) void softmax_k(
    const float* __restrict__ scp, float* __restrict__ s)
{
    __shared__ float red[8];
    const int b = blockIdx.x >> 6, d = blockIdx.x & 63;
    const int t = threadIdx.x;
    const float scale = 1.f / 24.f;

    float v[3];
#pragma unroll
    for (int u = 0; u < 3; u++) {
        int e = t + u * 256;
        if (e < 576) {
            int c = e / 9, k = e - c * 9;
            float sum = 0.f;
#pragma unroll
            for (int chn = 0; chn < 4; chn++)
                sum += scp[((size_t)((chn * 16 + b) * 9 + k)) * 4096 + c * 64 + d];
            v[u] = sum * scale;
        } else v[u] = -3.4e38f;
    }

    float m = fmaxf(fmaxf(v[0], v[1]), v[2]);
#pragma unroll
    for (int o = 16; o; o >>= 1) m = fmaxf(m, __shfl_xor_sync(0xffffffffu, m, o));
    if ((t & 31) == 0) red[t >> 5] = m;
    __syncthreads();
    m = fmaxf(fmaxf(fmaxf(red[0], red[1]), fmaxf(red[2], red[3])),
              fmaxf(fmaxf(red[4], red[5]), fmaxf(red[6], red[7])));
    __syncthreads();

    float e0 = __expf(v[0] - m), e1 = __expf(v[1] - m);
    float e2 = (t + 512) < 576 ? __expf(v[2] - m) : 0.f;
    float sum = e0 + e1 + e2;
#pragma unroll
    for (int o = 16; o; o >>= 1) sum += __shfl_xor_sync(0xffffffffu, sum, o);
    if ((t & 31) == 0) red[t >> 5] = sum;
    __syncthreads();
    sum = red[0] + red[1] + red[2] + red[3] + red[4] + red[5] + red[6] + red[7];

    float inv = 1.f / sum;
    float* p = s + (size_t)(b * C_ + d) * 576;
    p[t] = e0 * inv;
    p[t + 256] = e1 * inv;
    if (t + 512 < 576) p[t + 512] = e2 * inv;
}

// ---------------- launch -----------------------------------------------------
extern "C" void kernel_launch(void* const* d_in, const int* in_sizes, int n_in,
                              void* d_out, int out_size)
{
    const float* x1 = (const float*)d_in[0];
    const float* x2 = (const float*)d_in[1];
    const float* w1 = (const float*)d_in[2];
    const float* w2 = (const float*)d_in[3];
    const float* w3 = (const float*)d_in[4];
    float* out = (float*)d_out;

    float *kf, *qf, *sc, *scp;
    __half *Xh, *Xl, *Bh, *Bl;
    cudaGetSymbolAddress((void**)&kf, g_kf);
    cudaGetSymbolAddress((void**)&qf, g_qf);
    cudaGetSymbolAddress((void**)&sc, g_sc);
    cudaGetSymbolAddress((void**)&scp, g_scp);
    cudaGetSymbolAddress((void**)&Xh, g_Xh);
    cudaGetSymbolAddress((void**)&Xl, g_Xl);
    cudaGetSymbolAddress((void**)&Bh, g_Bh);
    cudaGetSymbolAddress((void**)&Bl, g_Bl);

    cudaFuncSetAttribute(conv_mma_k, cudaFuncAttributeMaxDynamicSharedMemorySize, SMEMSZ);

    convert_x_k<<<dim3(96, 16, 2), 256>>>(x1, x2, Xh, Xl);
    convert_w_k<<<dim3(576, 1), 64>>>(w1, Bh, Bl, 0, 0, 0);
    convert_w_k<<<dim3(576, 1), 64>>>(w2, Bh, Bl, 576, 0, 0);
    convert_w_k<<<dim3(576, 1), 64>>>(w3, Bh, Bl, 1152, 0, 0);

    dim3 g(6, 12, 16);
    conv_mma_k<<<g, 256, SMEMSZ>>>(Xh, Xl, Bh, Bl, 0, 0, 0, 0, kf, 0, 0);      // kf
    conv_mma_k<<<g, 256, SMEMSZ>>>(Xh, Xl, Bh, Bl, 16, 576, 0, 0, qf, 0, 0);   // qf
    conv_mma_k<<<g, 256, SMEMSZ>>>(Xh, Xl, Bh, Bl, 0, 1152, 0, 1, 0, Xh, Xl);  // vf

    scores_k<<<dim3(9, 4, 16), 256>>>(kf, qf, scp);
    softmax_k<<<B_ * C_, 256>>>(scp, sc);
    convert_w_k<<<dim3(576, 16), 64>>>(sc, Bh, Bl, 1728, C_ * 576, 576);

    conv_mma_k<<<g, 256, SMEMSZ>>>(Xh, Xl, Bh, Bl, 32, 1728, 576, 0, out, 0, 0); // dyn
}